// round 1
// baseline (speedup 1.0000x reference)
#include <cuda_runtime.h>
#include <math_constants.h>

#define NNODES 100000
#define NEDGES 1600000

// ---------------- scratch (static __device__ — no allocs allowed) ----------------
__device__ float g_m[(size_t)NNODES * 384];       // projected messages [N][3*128]
__device__ float g_feats[(size_t)NNODES * 1536];  // PNA features [N][3*512]
__device__ int   g_rowptr[NNODES + 1];

// ---------------- row pointers from sorted rows ----------------
__global__ void k_rowptr(const int* __restrict__ rows, int E, int N) {
    int i = blockIdx.x * blockDim.x + threadIdx.x;
    if (i > N) return;
    int lo = 0, hi = E;
    while (lo < hi) {
        int mid = (lo + hi) >> 1;
        if (__ldg(rows + mid) < i) lo = mid + 1; else hi = mid;
    }
    g_rowptr[i] = lo;
}

// ---------------- projection GEMM: m = x @ [W | W2 | W3]  ----------------
// grid: (ceil(N/64), 6). slab s covers output cols [s*64, s*64+64) of 384.
__global__ __launch_bounds__(256) void k_proj(const float* __restrict__ x,
                                              const float* __restrict__ W,
                                              const float* __restrict__ W2,
                                              const float* __restrict__ W3, int N) {
    __shared__ float As[64][64];  // [row][k]
    __shared__ float Bs[64][64];  // [k][col]
    const int bm = blockIdx.x * 64;
    const int slab = blockIdx.y;                       // 0..5
    const float* Wp = (slab < 2) ? W : (slab < 4) ? W2 : W3;
    const int cb = (slab & 1) * 64;                    // local col base in its 128-wide W
    const int tid = threadIdx.x;
    const int tx = tid & 15, ty = tid >> 4;
    float acc[4][4] = {};

    for (int kc = 0; kc < 128; kc += 64) {
#pragma unroll
        for (int l = 0; l < 4; l++) {
            int idx = tid + 256 * l;
            int r = idx >> 4;
            int kp = (idx & 15) << 2;
            int gr = bm + r; if (gr >= N) gr = N - 1;
            float4 v = *(const float4*)&x[(size_t)gr * 128 + kc + kp];
            *(float4*)&As[r][kp] = v;
            float4 w = *(const float4*)&Wp[(size_t)(kc + r) * 128 + cb + kp];
            *(float4*)&Bs[r][kp] = w;
        }
        __syncthreads();
#pragma unroll
        for (int k = 0; k < 64; k++) {
            float a0 = As[ty * 4 + 0][k];
            float a1 = As[ty * 4 + 1][k];
            float a2 = As[ty * 4 + 2][k];
            float a3 = As[ty * 4 + 3][k];
            float4 b = *(float4*)&Bs[k][tx * 4];
            acc[0][0] += a0 * b.x; acc[0][1] += a0 * b.y; acc[0][2] += a0 * b.z; acc[0][3] += a0 * b.w;
            acc[1][0] += a1 * b.x; acc[1][1] += a1 * b.y; acc[1][2] += a1 * b.z; acc[1][3] += a1 * b.w;
            acc[2][0] += a2 * b.x; acc[2][1] += a2 * b.y; acc[2][2] += a2 * b.z; acc[2][3] += a2 * b.w;
            acc[3][0] += a3 * b.x; acc[3][1] += a3 * b.y; acc[3][2] += a3 * b.z; acc[3][3] += a3 * b.w;
        }
        __syncthreads();
    }
    const int colg = slab * 64 + tx * 4;  // global col in [0,384)
#pragma unroll
    for (int i = 0; i < 4; i++) {
        int gr = bm + ty * 4 + i;
        if (gr < N) {
            float4 o = make_float4(acc[i][0], acc[i][1], acc[i][2], acc[i][3]);
            *(float4*)&g_m[(size_t)gr * 384 + colg] = o;
        }
    }
}

// ---------------- aggregation: warp-per-node segment mean/max/min/std ----------------
__device__ __forceinline__ void agg_upd(float4 v, float s, float4& su, float4& sq,
                                        float4& mx, float4& mn) {
    float gx = v.x * s, gy = v.y * s, gz = v.z * s, gw = v.w * s;
    su.x += gx; su.y += gy; su.z += gz; su.w += gw;
    sq.x += gx * gx; sq.y += gy * gy; sq.z += gz * gz; sq.w += gw * gw;
    mx.x = fmaxf(mx.x, gx); mx.y = fmaxf(mx.y, gy); mx.z = fmaxf(mx.z, gz); mx.w = fmaxf(mx.w, gw);
    mn.x = fminf(mn.x, gx); mn.y = fminf(mn.y, gy); mn.z = fminf(mn.z, gz); mn.w = fminf(mn.w, gw);
}

__device__ __forceinline__ void agg_finish(int deg, float inv, float4 su, float4 sq,
                                           float4 mx, float4 mn, float* base) {
    float4 mean, var, sd;
    mean.x = su.x * inv; mean.y = su.y * inv; mean.z = su.z * inv; mean.w = su.w * inv;
    var.x = fmaxf(sq.x * inv - mean.x * mean.x, 0.f);
    var.y = fmaxf(sq.y * inv - mean.y * mean.y, 0.f);
    var.z = fmaxf(sq.z * inv - mean.z * mean.z, 0.f);
    var.w = fmaxf(sq.w * inv - mean.w * mean.w, 0.f);
    sd.x = sqrtf(var.x + 1e-5f); sd.y = sqrtf(var.y + 1e-5f);
    sd.z = sqrtf(var.z + 1e-5f); sd.w = sqrtf(var.w + 1e-5f);
    if (deg == 0) {
        mx = make_float4(0.f, 0.f, 0.f, 0.f);
        mn = make_float4(0.f, 0.f, 0.f, 0.f);
    }
    *(float4*)(base)       = mean;
    *(float4*)(base + 128) = mx;
    *(float4*)(base + 256) = mn;
    *(float4*)(base + 384) = sd;
}

__global__ __launch_bounds__(256) void k_agg(const int* __restrict__ cols,
                                             const float* __restrict__ vA,
                                             const float* __restrict__ vC, int N) {
    int warp = (blockIdx.x * blockDim.x + threadIdx.x) >> 5;
    int lane = threadIdx.x & 31;
    if (warp >= N) return;
    const int r0 = g_rowptr[warp], r1 = g_rowptr[warp + 1];

    const float NEG = -CUDART_INF_F, POS = CUDART_INF_F;
    float4 s1 = {0, 0, 0, 0}, q1 = {0, 0, 0, 0};
    float4 s2 = {0, 0, 0, 0}, q2 = {0, 0, 0, 0};
    float4 s3 = {0, 0, 0, 0}, q3 = {0, 0, 0, 0};
    float4 x1 = {NEG, NEG, NEG, NEG}, n1 = {POS, POS, POS, POS};
    float4 x2 = x1, n2 = n1, x3 = x1, n3 = n1;

    for (int e = r0; e < r1; e++) {
        int c = __ldg(cols + e);
        float a = __ldg(vA + e);
        float b = __ldg(vC + e);
        float h = a * b;
        const float* p = g_m + (size_t)c * 384 + lane * 4;
        float4 v1 = *(const float4*)(p);
        float4 v2 = *(const float4*)(p + 128);
        float4 v3 = *(const float4*)(p + 256);
        agg_upd(v1, a, s1, q1, x1, n1);
        agg_upd(v2, b, s2, q2, x2, n2);
        agg_upd(v3, h, s3, q3, x3, n3);
    }
    const int deg = r1 - r0;
    const float inv = 1.f / fmaxf((float)deg, 1.f);
    float* fb = g_feats + (size_t)warp * 1536 + lane * 4;
    agg_finish(deg, inv, s1, q1, x1, n1, fb);
    agg_finish(deg, inv, s2, q2, x2, n2, fb + 512);
    agg_finish(deg, inv, s3, q3, x3, n3, fb + 1024);
}

// ---------------- output GEMM: out = feats @ pna_w_flat[1536,128] + sum(pna_b) ----------------
__global__ __launch_bounds__(256) void k_out(const float* __restrict__ pw,
                                             const float* __restrict__ pb,
                                             float* __restrict__ out, int N) {
    __shared__ float As[64][32];   // [row][k]
    __shared__ float Bs[32][128];  // [k][col]
    const int bm = blockIdx.x * 64;
    const int tid = threadIdx.x;
    const int tx = tid & 15, ty = tid >> 4;  // thread: rows ty*4.., cols tx*8..
    float acc[4][8] = {};

    for (int kc = 0; kc < 1536; kc += 32) {
#pragma unroll
        for (int l = 0; l < 2; l++) {
            int idx = tid + 256 * l;
            int r = idx >> 3;
            int kp = (idx & 7) << 2;
            int gr = bm + r; if (gr >= N) gr = N - 1;
            *(float4*)&As[r][kp] = *(const float4*)&g_feats[(size_t)gr * 1536 + kc + kp];
        }
#pragma unroll
        for (int l = 0; l < 4; l++) {
            int idx = tid + 256 * l;
            int kk = idx >> 5;
            int jp = (idx & 31) << 2;
            *(float4*)&Bs[kk][jp] = *(const float4*)&pw[(size_t)(kc + kk) * 128 + jp];
        }
        __syncthreads();
#pragma unroll
        for (int k = 0; k < 32; k++) {
            float a0 = As[ty * 4 + 0][k];
            float a1 = As[ty * 4 + 1][k];
            float a2 = As[ty * 4 + 2][k];
            float a3 = As[ty * 4 + 3][k];
            float4 b0 = *(float4*)&Bs[k][tx * 8];
            float4 b1 = *(float4*)&Bs[k][tx * 8 + 4];
            acc[0][0] += a0 * b0.x; acc[0][1] += a0 * b0.y; acc[0][2] += a0 * b0.z; acc[0][3] += a0 * b0.w;
            acc[0][4] += a0 * b1.x; acc[0][5] += a0 * b1.y; acc[0][6] += a0 * b1.z; acc[0][7] += a0 * b1.w;
            acc[1][0] += a1 * b0.x; acc[1][1] += a1 * b0.y; acc[1][2] += a1 * b0.z; acc[1][3] += a1 * b0.w;
            acc[1][4] += a1 * b1.x; acc[1][5] += a1 * b1.y; acc[1][6] += a1 * b1.z; acc[1][7] += a1 * b1.w;
            acc[2][0] += a2 * b0.x; acc[2][1] += a2 * b0.y; acc[2][2] += a2 * b0.z; acc[2][3] += a2 * b0.w;
            acc[2][4] += a2 * b1.x; acc[2][5] += a2 * b1.y; acc[2][6] += a2 * b1.z; acc[2][7] += a2 * b1.w;
            acc[3][0] += a3 * b0.x; acc[3][1] += a3 * b0.y; acc[3][2] += a3 * b0.z; acc[3][3] += a3 * b0.w;
            acc[3][4] += a3 * b1.x; acc[3][5] += a3 * b1.y; acc[3][6] += a3 * b1.z; acc[3][7] += a3 * b1.w;
        }
        __syncthreads();
    }

    // bias = pna_b[0] + pna_b[1] + pna_b[2]
    const int j0 = tx * 8;
    float bias[8];
#pragma unroll
    for (int j = 0; j < 8; j++)
        bias[j] = __ldg(pb + j0 + j) + __ldg(pb + 128 + j0 + j) + __ldg(pb + 256 + j0 + j);

#pragma unroll
    for (int i = 0; i < 4; i++) {
        int gr = bm + ty * 4 + i;
        if (gr < N) {
            float4 o0 = make_float4(acc[i][0] + bias[0], acc[i][1] + bias[1],
                                    acc[i][2] + bias[2], acc[i][3] + bias[3]);
            float4 o1 = make_float4(acc[i][4] + bias[4], acc[i][5] + bias[5],
                                    acc[i][6] + bias[6], acc[i][7] + bias[7]);
            *(float4*)&out[(size_t)gr * 128 + j0]     = o0;
            *(float4*)&out[(size_t)gr * 128 + j0 + 4] = o1;
        }
    }
}

// ---------------- launch ----------------
extern "C" void kernel_launch(void* const* d_in, const int* in_sizes, int n_in,
                              void* d_out, int out_size) {
    const float* x    = (const float*)d_in[0];
    const int*   rows = (const int*)d_in[1];
    const int*   cols = (const int*)d_in[2];
    const float* vA   = (const float*)d_in[3];
    const float* vC   = (const float*)d_in[4];
    const float* W    = (const float*)d_in[5];
    const float* W2   = (const float*)d_in[6];
    const float* W3   = (const float*)d_in[7];
    const float* pw   = (const float*)d_in[8];  // [3,512,128] == flat [1536,128]
    const float* pb   = (const float*)d_in[9];  // [3,128]
    float* out = (float*)d_out;

    const int N = in_sizes[0] / 128;
    const int E = in_sizes[1];

    k_rowptr<<<(N + 1 + 255) / 256, 256>>>(rows, E, N);
    dim3 gproj((N + 63) / 64, 6);
    k_proj<<<gproj, 256>>>(x, W, W2, W3, N);
    k_agg<<<(N + 7) / 8, 256>>>(cols, vA, vC, N);
    k_out<<<(N + 63) / 64, 256>>>(pw, pb, out, N);
}

// round 2
// speedup vs baseline: 1.3173x; 1.3173x over previous
#include <cuda_runtime.h>
#include <math_constants.h>

#define NNODES 100000
#define NEDGES 1600000

// ---------------- scratch (static __device__ — no allocs allowed) ----------------
__device__ float g_m[(size_t)NNODES * 384];       // projected messages [N][3*128]
__device__ float g_feats[(size_t)NNODES * 1536];  // PNA features [N][3*512]
__device__ int   g_rowptr[NNODES + 1];

// ---------------- row pointers from sorted rows ----------------
__global__ void k_rowptr(const int* __restrict__ rows, int E, int N) {
    int i = blockIdx.x * blockDim.x + threadIdx.x;
    if (i > N) return;
    int lo = 0, hi = E;
    while (lo < hi) {
        int mid = (lo + hi) >> 1;
        if (__ldg(rows + mid) < i) lo = mid + 1; else hi = mid;
    }
    g_rowptr[i] = lo;
}

// ---------------- projection GEMM: m = x @ [W | W2 | W3]  ----------------
// 128x128 block tile, 8x8 per thread, K=128 (8 chunks of 16).
// grid: (ceil(N/128), 3); slab s uses weight matrix s, writes cols [s*128, s*128+128).
__global__ __launch_bounds__(256, 2) void k_proj(const float* __restrict__ x,
                                                 const float* __restrict__ W,
                                                 const float* __restrict__ W2,
                                                 const float* __restrict__ W3, int N) {
    __shared__ float As[128][16];
    __shared__ float Bs[16][128];
    const int bm = blockIdx.x * 128;
    const int slab = blockIdx.y;  // 0..2
    const float* Wp = (slab == 0) ? W : (slab == 1) ? W2 : W3;
    const int tid = threadIdx.x;
    const int tx = tid & 15, ty = tid >> 4;
    const int row0 = ty * 8, col0 = tx * 8;

    const int ar  = tid >> 2;          // 0..63 (+64 for second half)
    const int akp = (tid & 3) << 2;
    const int bkk = tid >> 5;          // 0..7 (+8 for second half)
    const int bjp = (tid & 31) << 2;

    int gr0 = bm + ar;      if (gr0 >= N) gr0 = N - 1;
    int gr1 = bm + ar + 64; if (gr1 >= N) gr1 = N - 1;

    float acc[8][8] = {};
    float4 pa0, pa1, pv0, pv1;

    pa0 = *(const float4*)&x[(size_t)gr0 * 128 + akp];
    pa1 = *(const float4*)&x[(size_t)gr1 * 128 + akp];
    pv0 = *(const float4*)&Wp[(size_t)bkk * 128 + bjp];
    pv1 = *(const float4*)&Wp[(size_t)(8 + bkk) * 128 + bjp];

    for (int kc = 0; kc < 128; kc += 16) {
        *(float4*)&As[ar][akp]      = pa0;
        *(float4*)&As[ar + 64][akp] = pa1;
        *(float4*)&Bs[bkk][bjp]     = pv0;
        *(float4*)&Bs[bkk + 8][bjp] = pv1;
        __syncthreads();
        const int kn = kc + 16;
        if (kn < 128) {
            pa0 = *(const float4*)&x[(size_t)gr0 * 128 + kn + akp];
            pa1 = *(const float4*)&x[(size_t)gr1 * 128 + kn + akp];
            pv0 = *(const float4*)&Wp[(size_t)(kn + bkk) * 128 + bjp];
            pv1 = *(const float4*)&Wp[(size_t)(kn + 8 + bkk) * 128 + bjp];
        }
#pragma unroll
        for (int k = 0; k < 16; k++) {
            float a[8];
#pragma unroll
            for (int i = 0; i < 8; i++) a[i] = As[row0 + i][k];
            float4 b0 = *(float4*)&Bs[k][col0];
            float4 b1 = *(float4*)&Bs[k][col0 + 4];
#pragma unroll
            for (int i = 0; i < 8; i++) {
                acc[i][0] += a[i] * b0.x; acc[i][1] += a[i] * b0.y;
                acc[i][2] += a[i] * b0.z; acc[i][3] += a[i] * b0.w;
                acc[i][4] += a[i] * b1.x; acc[i][5] += a[i] * b1.y;
                acc[i][6] += a[i] * b1.z; acc[i][7] += a[i] * b1.w;
            }
        }
        __syncthreads();
    }
    const int colg = slab * 128 + col0;
#pragma unroll
    for (int i = 0; i < 8; i++) {
        int gr = bm + row0 + i;
        if (gr < N) {
            float4 o0 = make_float4(acc[i][0], acc[i][1], acc[i][2], acc[i][3]);
            float4 o1 = make_float4(acc[i][4], acc[i][5], acc[i][6], acc[i][7]);
            *(float4*)&g_m[(size_t)gr * 384 + colg]     = o0;
            *(float4*)&g_m[(size_t)gr * 384 + colg + 4] = o1;
        }
    }
}

// ---------------- aggregation: warp-per-node segment mean/max/min/std ----------------
__device__ __forceinline__ void agg_upd(float4 v, float s, float4& su, float4& sq,
                                        float4& mx, float4& mn) {
    float gx = v.x * s, gy = v.y * s, gz = v.z * s, gw = v.w * s;
    su.x += gx; su.y += gy; su.z += gz; su.w += gw;
    sq.x += gx * gx; sq.y += gy * gy; sq.z += gz * gz; sq.w += gw * gw;
    mx.x = fmaxf(mx.x, gx); mx.y = fmaxf(mx.y, gy); mx.z = fmaxf(mx.z, gz); mx.w = fmaxf(mx.w, gw);
    mn.x = fminf(mn.x, gx); mn.y = fminf(mn.y, gy); mn.z = fminf(mn.z, gz); mn.w = fminf(mn.w, gw);
}

__device__ __forceinline__ void agg_finish(int deg, float inv, float4 su, float4 sq,
                                           float4 mx, float4 mn, float* base) {
    float4 mean, var, sd;
    mean.x = su.x * inv; mean.y = su.y * inv; mean.z = su.z * inv; mean.w = su.w * inv;
    var.x = fmaxf(sq.x * inv - mean.x * mean.x, 0.f);
    var.y = fmaxf(sq.y * inv - mean.y * mean.y, 0.f);
    var.z = fmaxf(sq.z * inv - mean.z * mean.z, 0.f);
    var.w = fmaxf(sq.w * inv - mean.w * mean.w, 0.f);
    sd.x = sqrtf(var.x + 1e-5f); sd.y = sqrtf(var.y + 1e-5f);
    sd.z = sqrtf(var.z + 1e-5f); sd.w = sqrtf(var.w + 1e-5f);
    if (deg == 0) {
        mx = make_float4(0.f, 0.f, 0.f, 0.f);
        mn = make_float4(0.f, 0.f, 0.f, 0.f);
    }
    *(float4*)(base)       = mean;
    *(float4*)(base + 128) = mx;
    *(float4*)(base + 256) = mn;
    *(float4*)(base + 384) = sd;
}

__global__ __launch_bounds__(256) void k_agg(const int* __restrict__ cols,
                                             const float* __restrict__ vA,
                                             const float* __restrict__ vC, int N) {
    int warp = (blockIdx.x * blockDim.x + threadIdx.x) >> 5;
    int lane = threadIdx.x & 31;
    if (warp >= N) return;
    const int r0 = g_rowptr[warp], r1 = g_rowptr[warp + 1];

    const float NEG = -CUDART_INF_F, POS = CUDART_INF_F;
    float4 s1 = {0, 0, 0, 0}, q1 = {0, 0, 0, 0};
    float4 s2 = {0, 0, 0, 0}, q2 = {0, 0, 0, 0};
    float4 s3 = {0, 0, 0, 0}, q3 = {0, 0, 0, 0};
    float4 x1 = {NEG, NEG, NEG, NEG}, n1 = {POS, POS, POS, POS};
    float4 x2 = x1, n2 = n1, x3 = x1, n3 = n1;

    for (int e = r0; e < r1; e++) {
        int c = __ldg(cols + e);
        float a = __ldg(vA + e);
        float b = __ldg(vC + e);
        float h = a * b;
        const float* p = g_m + (size_t)c * 384 + lane * 4;
        float4 v1 = *(const float4*)(p);
        float4 v2 = *(const float4*)(p + 128);
        float4 v3 = *(const float4*)(p + 256);
        agg_upd(v1, a, s1, q1, x1, n1);
        agg_upd(v2, b, s2, q2, x2, n2);
        agg_upd(v3, h, s3, q3, x3, n3);
    }
    const int deg = r1 - r0;
    const float inv = 1.f / fmaxf((float)deg, 1.f);
    float* fb = g_feats + (size_t)warp * 1536 + lane * 4;
    agg_finish(deg, inv, s1, q1, x1, n1, fb);
    agg_finish(deg, inv, s2, q2, x2, n2, fb + 512);
    agg_finish(deg, inv, s3, q3, x3, n3, fb + 1024);
}

// ---------------- output GEMM: out = feats @ pna_w_flat[1536,128] + sum(pna_b) ----------------
// 128x128 block tile, 8x8 per thread, K=1536 (96 chunks of 16), register prefetch.
__global__ __launch_bounds__(256, 2) void k_out(const float* __restrict__ pw,
                                                const float* __restrict__ pb,
                                                float* __restrict__ out, int N) {
    __shared__ float As[128][16];
    __shared__ float Bs[16][128];
    const int bm = blockIdx.x * 128;
    const int tid = threadIdx.x;
    const int tx = tid & 15, ty = tid >> 4;
    const int row0 = ty * 8, col0 = tx * 8;

    const int ar  = tid >> 2;
    const int akp = (tid & 3) << 2;
    const int bkk = tid >> 5;
    const int bjp = (tid & 31) << 2;

    int gr0 = bm + ar;      if (gr0 >= N) gr0 = N - 1;
    int gr1 = bm + ar + 64; if (gr1 >= N) gr1 = N - 1;

    float acc[8][8] = {};
    float4 pa0, pa1, pv0, pv1;

    pa0 = *(const float4*)&g_feats[(size_t)gr0 * 1536 + akp];
    pa1 = *(const float4*)&g_feats[(size_t)gr1 * 1536 + akp];
    pv0 = *(const float4*)&pw[(size_t)bkk * 128 + bjp];
    pv1 = *(const float4*)&pw[(size_t)(8 + bkk) * 128 + bjp];

    for (int kc = 0; kc < 1536; kc += 16) {
        *(float4*)&As[ar][akp]      = pa0;
        *(float4*)&As[ar + 64][akp] = pa1;
        *(float4*)&Bs[bkk][bjp]     = pv0;
        *(float4*)&Bs[bkk + 8][bjp] = pv1;
        __syncthreads();
        const int kn = kc + 16;
        if (kn < 1536) {
            pa0 = *(const float4*)&g_feats[(size_t)gr0 * 1536 + kn + akp];
            pa1 = *(const float4*)&g_feats[(size_t)gr1 * 1536 + kn + akp];
            pv0 = *(const float4*)&pw[(size_t)(kn + bkk) * 128 + bjp];
            pv1 = *(const float4*)&pw[(size_t)(kn + 8 + bkk) * 128 + bjp];
        }
#pragma unroll
        for (int k = 0; k < 16; k++) {
            float a[8];
#pragma unroll
            for (int i = 0; i < 8; i++) a[i] = As[row0 + i][k];
            float4 b0 = *(float4*)&Bs[k][col0];
            float4 b1 = *(float4*)&Bs[k][col0 + 4];
#pragma unroll
            for (int i = 0; i < 8; i++) {
                acc[i][0] += a[i] * b0.x; acc[i][1] += a[i] * b0.y;
                acc[i][2] += a[i] * b0.z; acc[i][3] += a[i] * b0.w;
                acc[i][4] += a[i] * b1.x; acc[i][5] += a[i] * b1.y;
                acc[i][6] += a[i] * b1.z; acc[i][7] += a[i] * b1.w;
            }
        }
        __syncthreads();
    }

    float bias[8];
#pragma unroll
    for (int j = 0; j < 8; j++)
        bias[j] = __ldg(pb + col0 + j) + __ldg(pb + 128 + col0 + j) + __ldg(pb + 256 + col0 + j);

#pragma unroll
    for (int i = 0; i < 8; i++) {
        int gr = bm + row0 + i;
        if (gr < N) {
            float4 o0 = make_float4(acc[i][0] + bias[0], acc[i][1] + bias[1],
                                    acc[i][2] + bias[2], acc[i][3] + bias[3]);
            float4 o1 = make_float4(acc[i][4] + bias[4], acc[i][5] + bias[5],
                                    acc[i][6] + bias[6], acc[i][7] + bias[7]);
            *(float4*)&out[(size_t)gr * 128 + col0]     = o0;
            *(float4*)&out[(size_t)gr * 128 + col0 + 4] = o1;
        }
    }
}

// ---------------- launch ----------------
extern "C" void kernel_launch(void* const* d_in, const int* in_sizes, int n_in,
                              void* d_out, int out_size) {
    const float* x    = (const float*)d_in[0];
    const int*   rows = (const int*)d_in[1];
    const int*   cols = (const int*)d_in[2];
    const float* vA   = (const float*)d_in[3];
    const float* vC   = (const float*)d_in[4];
    const float* W    = (const float*)d_in[5];
    const float* W2   = (const float*)d_in[6];
    const float* W3   = (const float*)d_in[7];
    const float* pw   = (const float*)d_in[8];  // [3,512,128] == flat [1536,128]
    const float* pb   = (const float*)d_in[9];  // [3,128]
    float* out = (float*)d_out;

    const int N = in_sizes[0] / 128;
    const int E = in_sizes[1];

    k_rowptr<<<(N + 1 + 255) / 256, 256>>>(rows, E, N);
    dim3 gproj((N + 127) / 128, 3);
    k_proj<<<gproj, 256>>>(x, W, W2, W3, N);
    k_agg<<<(N + 7) / 8, 256>>>(cols, vA, vC, N);
    k_out<<<(N + 127) / 128, 256>>>(pw, pb, out, N);
}

// round 4
// speedup vs baseline: 1.3746x; 1.0435x over previous
#include <cuda_runtime.h>
#include <math_constants.h>
#include <cstdint>

#define NNODES 100000
#define NEDGES 1600000

// ---------------- scratch (static __device__ — no allocs allowed) ----------------
__device__ float g_m[(size_t)NNODES * 384];       // projected messages [N][3*128]
__device__ float g_feats[(size_t)NNODES * 1536];  // PNA features [N][3*512]
__device__ int   g_rowptr[NNODES + 1];

// ---------------- cp.async helpers ----------------
__device__ __forceinline__ void cpasync16(unsigned int dst, const float* src) {
    asm volatile("cp.async.cg.shared.global [%0], [%1], 16;\n" :: "r"(dst), "l"(src));
}
__device__ __forceinline__ void cp_commit() {
    asm volatile("cp.async.commit_group;\n" ::);
}
__device__ __forceinline__ void cp_wait1() {
    asm volatile("cp.async.wait_group 1;\n" ::);
}

// ---------------- row pointers from sorted rows ----------------
__global__ void k_rowptr(const int* __restrict__ rows, int E, int N) {
    int i = blockIdx.x * blockDim.x + threadIdx.x;
    if (i > N) return;
    int lo = 0, hi = E;
    while (lo < hi) {
        int mid = (lo + hi) >> 1;
        if (__ldg(rows + mid) < i) lo = mid + 1; else hi = mid;
    }
    g_rowptr[i] = lo;
}

// ---------------- GEMM inner: 4-k group, vectorized A+B reads ----------------
#define GEMM_COMPUTE_CHUNK(ASBUF, BSBUF)                                          \
    _Pragma("unroll")                                                             \
    for (int g = 0; g < 4; g++) {                                                 \
        float4 b0[4], b1[4];                                                      \
        _Pragma("unroll")                                                         \
        for (int k = 0; k < 4; k++) {                                             \
            b0[k] = *(const float4*)&(BSBUF)[g * 4 + k][col0];                    \
            b1[k] = *(const float4*)&(BSBUF)[g * 4 + k][col0 + 4];                \
        }                                                                         \
        _Pragma("unroll")                                                         \
        for (int r = 0; r < 8; r++) {                                             \
            float4 a = *(const float4*)&(ASBUF)[row0 + r][g * 4];                 \
            float av[4] = {a.x, a.y, a.z, a.w};                                   \
            _Pragma("unroll")                                                     \
            for (int k = 0; k < 4; k++) {                                         \
                acc[r][0] += av[k] * b0[k].x; acc[r][1] += av[k] * b0[k].y;       \
                acc[r][2] += av[k] * b0[k].z; acc[r][3] += av[k] * b0[k].w;       \
                acc[r][4] += av[k] * b1[k].x; acc[r][5] += av[k] * b1[k].y;       \
                acc[r][6] += av[k] * b1[k].z; acc[r][7] += av[k] * b1[k].w;       \
            }                                                                     \
        }                                                                         \
    }

// ---------------- projection GEMM: m = x @ [W | W2 | W3] ----------------
// 128x128 tile, 8x8/thread, K=128 (8 chunks of 16), cp.async double buffer.
__global__ __launch_bounds__(256, 2) void k_proj(const float* __restrict__ x,
                                                 const float* __restrict__ W,
                                                 const float* __restrict__ W2,
                                                 const float* __restrict__ W3, int N) {
    __shared__ float As[2][128][16];
    __shared__ float Bs[2][16][128];
    const int bm = blockIdx.x * 128;
    const int slab = blockIdx.y;  // 0..2
    const float* Wp = (slab == 0) ? W : (slab == 1) ? W2 : W3;
    const int tid = threadIdx.x;
    const int tx = tid & 15, ty = tid >> 4;
    const int row0 = ty * 8, col0 = tx * 8;

    const int ar0  = tid >> 2;         // 0..63
    const int akq  = (tid & 3) << 2;   // 0,4,8,12
    const int bkk0 = tid >> 5;         // 0..7
    const int bjq  = (tid & 31) << 2;

    int gr0 = bm + ar0;      if (gr0 >= N) gr0 = N - 1;
    int gr1 = bm + ar0 + 64; if (gr1 >= N) gr1 = N - 1;
    const float* sA0 = x + (size_t)gr0 * 128 + akq;
    const float* sA1 = x + (size_t)gr1 * 128 + akq;
    const float* sB0 = Wp + (size_t)bkk0 * 128 + bjq;
    const float* sB1 = Wp + (size_t)(bkk0 + 8) * 128 + bjq;

    const unsigned int dA0 = (unsigned int)__cvta_generic_to_shared(&As[0][ar0][akq]);
    const unsigned int dA1 = (unsigned int)__cvta_generic_to_shared(&As[0][ar0 + 64][akq]);
    const unsigned int dB0 = (unsigned int)__cvta_generic_to_shared(&Bs[0][bkk0][bjq]);
    const unsigned int dB1 = (unsigned int)__cvta_generic_to_shared(&Bs[0][bkk0 + 8][bjq]);

    const int NK = 8;
#pragma unroll
    for (int p = 0; p < 2; p++) {
        cpasync16(dA0 + p * 8192, sA0 + p * 16);
        cpasync16(dA1 + p * 8192, sA1 + p * 16);
        cpasync16(dB0 + p * 8192, sB0 + (size_t)p * 2048);
        cpasync16(dB1 + p * 8192, sB1 + (size_t)p * 2048);
        cp_commit();
    }

    float acc[8][8] = {};
    for (int i = 0; i < NK; i++) {
        cp_wait1();
        __syncthreads();
        const int buf = i & 1;
        if (buf == 0) { GEMM_COMPUTE_CHUNK(As[0], Bs[0]); }
        else          { GEMM_COMPUTE_CHUNK(As[1], Bs[1]); }
        __syncthreads();
        const int nc = i + 2;
        if (nc < NK) {
            cpasync16(dA0 + buf * 8192, sA0 + nc * 16);
            cpasync16(dA1 + buf * 8192, sA1 + nc * 16);
            cpasync16(dB0 + buf * 8192, sB0 + (size_t)nc * 2048);
            cpasync16(dB1 + buf * 8192, sB1 + (size_t)nc * 2048);
        }
        cp_commit();
    }

    const int colg = slab * 128 + col0;
#pragma unroll
    for (int i = 0; i < 8; i++) {
        int gr = bm + row0 + i;
        if (gr < N) {
            float4 o0 = make_float4(acc[i][0], acc[i][1], acc[i][2], acc[i][3]);
            float4 o1 = make_float4(acc[i][4], acc[i][5], acc[i][6], acc[i][7]);
            *(float4*)&g_m[(size_t)gr * 384 + colg]     = o0;
            *(float4*)&g_m[(size_t)gr * 384 + colg + 4] = o1;
        }
    }
}

// ---------------- aggregation: warp-per-node segment mean/max/min/std ----------------
__device__ __forceinline__ void agg_upd(float4 v, float s, float4& su, float4& sq,
                                        float4& mx, float4& mn) {
    float gx = v.x * s, gy = v.y * s, gz = v.z * s, gw = v.w * s;
    su.x += gx; su.y += gy; su.z += gz; su.w += gw;
    sq.x += gx * gx; sq.y += gy * gy; sq.z += gz * gz; sq.w += gw * gw;
    mx.x = fmaxf(mx.x, gx); mx.y = fmaxf(mx.y, gy); mx.z = fmaxf(mx.z, gz); mx.w = fmaxf(mx.w, gw);
    mn.x = fminf(mn.x, gx); mn.y = fminf(mn.y, gy); mn.z = fminf(mn.z, gz); mn.w = fminf(mn.w, gw);
}

__device__ __forceinline__ void agg_finish(int deg, float inv, float4 su, float4 sq,
                                           float4 mx, float4 mn, float* base) {
    float4 mean, var, sd;
    mean.x = su.x * inv; mean.y = su.y * inv; mean.z = su.z * inv; mean.w = su.w * inv;
    var.x = fmaxf(sq.x * inv - mean.x * mean.x, 0.f);
    var.y = fmaxf(sq.y * inv - mean.y * mean.y, 0.f);
    var.z = fmaxf(sq.z * inv - mean.z * mean.z, 0.f);
    var.w = fmaxf(sq.w * inv - mean.w * mean.w, 0.f);
    sd.x = sqrtf(var.x + 1e-5f); sd.y = sqrtf(var.y + 1e-5f);
    sd.z = sqrtf(var.z + 1e-5f); sd.w = sqrtf(var.w + 1e-5f);
    if (deg == 0) {
        mx = make_float4(0.f, 0.f, 0.f, 0.f);
        mn = make_float4(0.f, 0.f, 0.f, 0.f);
    }
    *(float4*)(base)       = mean;
    *(float4*)(base + 128) = mx;
    *(float4*)(base + 256) = mn;
    *(float4*)(base + 384) = sd;
}

__global__ __launch_bounds__(256) void k_agg(const int* __restrict__ cols,
                                             const float* __restrict__ vA,
                                             const float* __restrict__ vC, int N) {
    int warp = (blockIdx.x * blockDim.x + threadIdx.x) >> 5;
    int lane = threadIdx.x & 31;
    if (warp >= N) return;
    const int r0 = g_rowptr[warp], r1 = g_rowptr[warp + 1];

    const float NEG = -CUDART_INF_F, POS = CUDART_INF_F;
    float4 s1 = {0, 0, 0, 0}, q1 = {0, 0, 0, 0};
    float4 s2 = {0, 0, 0, 0}, q2 = {0, 0, 0, 0};
    float4 s3 = {0, 0, 0, 0}, q3 = {0, 0, 0, 0};
    float4 x1 = {NEG, NEG, NEG, NEG}, n1 = {POS, POS, POS, POS};
    float4 x2 = x1, n2 = n1, x3 = x1, n3 = n1;

    for (int e = r0; e < r1; e++) {
        int c = __ldg(cols + e);
        float a = __ldg(vA + e);
        float b = __ldg(vC + e);
        float h = a * b;
        const float* p = g_m + (size_t)c * 384 + lane * 4;
        float4 v1 = *(const float4*)(p);
        float4 v2 = *(const float4*)(p + 128);
        float4 v3 = *(const float4*)(p + 256);
        agg_upd(v1, a, s1, q1, x1, n1);
        agg_upd(v2, b, s2, q2, x2, n2);
        agg_upd(v3, h, s3, q3, x3, n3);
    }
    const int deg = r1 - r0;
    const float inv = 1.f / fmaxf((float)deg, 1.f);
    float* fb = g_feats + (size_t)warp * 1536 + lane * 4;
    agg_finish(deg, inv, s1, q1, x1, n1, fb);
    agg_finish(deg, inv, s2, q2, x2, n2, fb + 512);
    agg_finish(deg, inv, s3, q3, x3, n3, fb + 1024);
}

// ---------------- output GEMM: out = feats @ pna_w_flat[1536,128] + sum(pna_b) ----------------
// 128x128 tile, 8x8/thread, K=1536 (96 chunks of 16), cp.async double buffer.
__global__ __launch_bounds__(256, 2) void k_out(const float* __restrict__ pw,
                                                const float* __restrict__ pb,
                                                float* __restrict__ out, int N) {
    __shared__ float As[2][128][16];
    __shared__ float Bs[2][16][128];
    const int bm = blockIdx.x * 128;
    const int tid = threadIdx.x;
    const int tx = tid & 15, ty = tid >> 4;
    const int row0 = ty * 8, col0 = tx * 8;

    const int ar0  = tid >> 2;
    const int akq  = (tid & 3) << 2;
    const int bkk0 = tid >> 5;
    const int bjq  = (tid & 31) << 2;

    int gr0 = bm + ar0;      if (gr0 >= N) gr0 = N - 1;
    int gr1 = bm + ar0 + 64; if (gr1 >= N) gr1 = N - 1;
    const float* sA0 = g_feats + (size_t)gr0 * 1536 + akq;
    const float* sA1 = g_feats + (size_t)gr1 * 1536 + akq;
    const float* sB0 = pw + (size_t)bkk0 * 128 + bjq;
    const float* sB1 = pw + (size_t)(bkk0 + 8) * 128 + bjq;

    const unsigned int dA0 = (unsigned int)__cvta_generic_to_shared(&As[0][ar0][akq]);
    const unsigned int dA1 = (unsigned int)__cvta_generic_to_shared(&As[0][ar0 + 64][akq]);
    const unsigned int dB0 = (unsigned int)__cvta_generic_to_shared(&Bs[0][bkk0][bjq]);
    const unsigned int dB1 = (unsigned int)__cvta_generic_to_shared(&Bs[0][bkk0 + 8][bjq]);

    const int NK = 96;
#pragma unroll
    for (int p = 0; p < 2; p++) {
        cpasync16(dA0 + p * 8192, sA0 + p * 16);
        cpasync16(dA1 + p * 8192, sA1 + p * 16);
        cpasync16(dB0 + p * 8192, sB0 + (size_t)p * 2048);
        cpasync16(dB1 + p * 8192, sB1 + (size_t)p * 2048);
        cp_commit();
    }

    float acc[8][8] = {};
    for (int i = 0; i < NK; i++) {
        cp_wait1();
        __syncthreads();
        const int buf = i & 1;
        if (buf == 0) { GEMM_COMPUTE_CHUNK(As[0], Bs[0]); }
        else          { GEMM_COMPUTE_CHUNK(As[1], Bs[1]); }
        __syncthreads();
        const int nc = i + 2;
        if (nc < NK) {
            cpasync16(dA0 + buf * 8192, sA0 + nc * 16);
            cpasync16(dA1 + buf * 8192, sA1 + nc * 16);
            cpasync16(dB0 + buf * 8192, sB0 + (size_t)nc * 2048);
            cpasync16(dB1 + buf * 8192, sB1 + (size_t)nc * 2048);
        }
        cp_commit();
    }

    float bias[8];
#pragma unroll
    for (int j = 0; j < 8; j++)
        bias[j] = __ldg(pb + col0 + j) + __ldg(pb + 128 + col0 + j) + __ldg(pb + 256 + col0 + j);

#pragma unroll
    for (int i = 0; i < 8; i++) {
        int gr = bm + row0 + i;
        if (gr < N) {
            float4 o0 = make_float4(acc[i][0] + bias[0], acc[i][1] + bias[1],
                                    acc[i][2] + bias[2], acc[i][3] + bias[3]);
            float4 o1 = make_float4(acc[i][4] + bias[4], acc[i][5] + bias[5],
                                    acc[i][6] + bias[6], acc[i][7] + bias[7]);
            *(float4*)&out[(size_t)gr * 128 + col0]     = o0;
            *(float4*)&out[(size_t)gr * 128 + col0 + 4] = o1;
        }
    }
}

// ---------------- launch ----------------
extern "C" void kernel_launch(void* const* d_in, const int* in_sizes, int n_in,
                              void* d_out, int out_size) {
    const float* x    = (const float*)d_in[0];
    const int*   rows = (const int*)d_in[1];
    const int*   cols = (const int*)d_in[2];
    const float* vA   = (const float*)d_in[3];
    const float* vC   = (const float*)d_in[4];
    const float* W    = (const float*)d_in[5];
    const float* W2   = (const float*)d_in[6];
    const float* W3   = (const float*)d_in[7];
    const float* pw   = (const float*)d_in[8];  // [3,512,128] == flat [1536,128]
    const float* pb   = (const float*)d_in[9];  // [3,128]
    float* out = (float*)d_out;

    const int N = in_sizes[0] / 128;
    const int E = in_sizes[1];

    k_rowptr<<<(N + 1 + 255) / 256, 256>>>(rows, E, N);
    dim3 gproj((N + 127) / 128, 3);
    k_proj<<<gproj, 256>>>(x, W, W2, W3, N);
    k_agg<<<(N + 7) / 8, 256>>>(cols, vA, vC, N);
    k_out<<<(N + 127) / 128, 256>>>(pw, pb, out, N);
}

// round 5
// speedup vs baseline: 2.2752x; 1.6552x over previous
#include <cuda_runtime.h>
#include <math_constants.h>
#include <cstdint>

#define NNODES 100000
#define NEDGES 1600000

// ---------------- scratch (static __device__ — no allocs allowed) ----------------
__device__ float g_m[(size_t)NNODES * 384];       // projected messages [N][3*128]
__device__ float g_feats[(size_t)NNODES * 1536];  // PNA features [N][3*512]
__device__ int   g_rowptr[NNODES + 1];

// ---------------- cp.async helpers ----------------
__device__ __forceinline__ void cpasync16(unsigned int dst, const float* src) {
    asm volatile("cp.async.cg.shared.global [%0], [%1], 16;\n" :: "r"(dst), "l"(src));
}
__device__ __forceinline__ void cp_commit() {
    asm volatile("cp.async.commit_group;\n" ::);
}
__device__ __forceinline__ void cp_wait1() {
    asm volatile("cp.async.wait_group 1;\n" ::);
}

// ---------------- tf32 warp MMA ----------------
__device__ __forceinline__ void mma_tf32(float* d, const unsigned* a, const unsigned* b) {
    asm volatile(
        "mma.sync.aligned.m16n8k8.row.col.f32.tf32.tf32.f32 "
        "{%0,%1,%2,%3},{%4,%5,%6,%7},{%8,%9},{%0,%1,%2,%3};\n"
        : "+f"(d[0]), "+f"(d[1]), "+f"(d[2]), "+f"(d[3])
        : "r"(a[0]), "r"(a[1]), "r"(a[2]), "r"(a[3]), "r"(b[0]), "r"(b[1]));
}

// ---------------- row pointers from sorted rows ----------------
__global__ void k_rowptr(const int* __restrict__ rows, int E, int N) {
    int i = blockIdx.x * blockDim.x + threadIdx.x;
    if (i > N) return;
    int lo = 0, hi = E;
    while (lo < hi) {
        int mid = (lo + hi) >> 1;
        if (__ldg(rows + mid) < i) lo = mid + 1; else hi = mid;
    }
    g_rowptr[i] = lo;
}

// ---------------- GEMM inner: 4-k group, vectorized A+B reads (fp32 SIMT) ----------------
#define GEMM_COMPUTE_CHUNK(ASBUF, BSBUF)                                          \
    _Pragma("unroll")                                                             \
    for (int g = 0; g < 4; g++) {                                                 \
        float4 b0[4], b1[4];                                                      \
        _Pragma("unroll")                                                         \
        for (int k = 0; k < 4; k++) {                                             \
            b0[k] = *(const float4*)&(BSBUF)[g * 4 + k][col0];                    \
            b1[k] = *(const float4*)&(BSBUF)[g * 4 + k][col0 + 4];                \
        }                                                                         \
        _Pragma("unroll")                                                         \
        for (int r = 0; r < 8; r++) {                                             \
            float4 a = *(const float4*)&(ASBUF)[row0 + r][g * 4];                 \
            float av[4] = {a.x, a.y, a.z, a.w};                                   \
            _Pragma("unroll")                                                     \
            for (int k = 0; k < 4; k++) {                                         \
                acc[r][0] += av[k] * b0[k].x; acc[r][1] += av[k] * b0[k].y;       \
                acc[r][2] += av[k] * b0[k].z; acc[r][3] += av[k] * b0[k].w;       \
                acc[r][4] += av[k] * b1[k].x; acc[r][5] += av[k] * b1[k].y;       \
                acc[r][6] += av[k] * b1[k].z; acc[r][7] += av[k] * b1[k].w;       \
            }                                                                     \
        }                                                                         \
    }

// ---------------- projection GEMM: m = x @ [W | W2 | W3] (fp32 SIMT) ----------------
__global__ __launch_bounds__(256, 2) void k_proj(const float* __restrict__ x,
                                                 const float* __restrict__ W,
                                                 const float* __restrict__ W2,
                                                 const float* __restrict__ W3, int N) {
    __shared__ float As[2][128][16];
    __shared__ float Bs[2][16][128];
    const int bm = blockIdx.x * 128;
    const int slab = blockIdx.y;  // 0..2
    const float* Wp = (slab == 0) ? W : (slab == 1) ? W2 : W3;
    const int tid = threadIdx.x;
    const int tx = tid & 15, ty = tid >> 4;
    const int row0 = ty * 8, col0 = tx * 8;

    const int ar0  = tid >> 2;
    const int akq  = (tid & 3) << 2;
    const int bkk0 = tid >> 5;
    const int bjq  = (tid & 31) << 2;

    int gr0 = bm + ar0;      if (gr0 >= N) gr0 = N - 1;
    int gr1 = bm + ar0 + 64; if (gr1 >= N) gr1 = N - 1;
    const float* sA0 = x + (size_t)gr0 * 128 + akq;
    const float* sA1 = x + (size_t)gr1 * 128 + akq;
    const float* sB0 = Wp + (size_t)bkk0 * 128 + bjq;
    const float* sB1 = Wp + (size_t)(bkk0 + 8) * 128 + bjq;

    const unsigned int dA0 = (unsigned int)__cvta_generic_to_shared(&As[0][ar0][akq]);
    const unsigned int dA1 = (unsigned int)__cvta_generic_to_shared(&As[0][ar0 + 64][akq]);
    const unsigned int dB0 = (unsigned int)__cvta_generic_to_shared(&Bs[0][bkk0][bjq]);
    const unsigned int dB1 = (unsigned int)__cvta_generic_to_shared(&Bs[0][bkk0 + 8][bjq]);

    const int NK = 8;
#pragma unroll
    for (int p = 0; p < 2; p++) {
        cpasync16(dA0 + p * 8192, sA0 + p * 16);
        cpasync16(dA1 + p * 8192, sA1 + p * 16);
        cpasync16(dB0 + p * 8192, sB0 + (size_t)p * 2048);
        cpasync16(dB1 + p * 8192, sB1 + (size_t)p * 2048);
        cp_commit();
    }

    float acc[8][8] = {};
    for (int i = 0; i < NK; i++) {
        cp_wait1();
        __syncthreads();
        const int buf = i & 1;
        if (buf == 0) { GEMM_COMPUTE_CHUNK(As[0], Bs[0]); }
        else          { GEMM_COMPUTE_CHUNK(As[1], Bs[1]); }
        __syncthreads();
        const int nc = i + 2;
        if (nc < NK) {
            cpasync16(dA0 + buf * 8192, sA0 + nc * 16);
            cpasync16(dA1 + buf * 8192, sA1 + nc * 16);
            cpasync16(dB0 + buf * 8192, sB0 + (size_t)nc * 2048);
            cpasync16(dB1 + buf * 8192, sB1 + (size_t)nc * 2048);
        }
        cp_commit();
    }

    const int colg = slab * 128 + col0;
#pragma unroll
    for (int i = 0; i < 8; i++) {
        int gr = bm + row0 + i;
        if (gr < N) {
            float4 o0 = make_float4(acc[i][0], acc[i][1], acc[i][2], acc[i][3]);
            float4 o1 = make_float4(acc[i][4], acc[i][5], acc[i][6], acc[i][7]);
            *(float4*)&g_m[(size_t)gr * 384 + colg]     = o0;
            *(float4*)&g_m[(size_t)gr * 384 + colg + 4] = o1;
        }
    }
}

// ---------------- aggregation: warp-per-node segment mean/max/min/std ----------------
__device__ __forceinline__ void agg_upd(float4 v, float s, float4& su, float4& sq,
                                        float4& mx, float4& mn) {
    float gx = v.x * s, gy = v.y * s, gz = v.z * s, gw = v.w * s;
    su.x += gx; su.y += gy; su.z += gz; su.w += gw;
    sq.x += gx * gx; sq.y += gy * gy; sq.z += gz * gz; sq.w += gw * gw;
    mx.x = fmaxf(mx.x, gx); mx.y = fmaxf(mx.y, gy); mx.z = fmaxf(mx.z, gz); mx.w = fmaxf(mx.w, gw);
    mn.x = fminf(mn.x, gx); mn.y = fminf(mn.y, gy); mn.z = fminf(mn.z, gz); mn.w = fminf(mn.w, gw);
}

__device__ __forceinline__ void agg_finish(int deg, float inv, float4 su, float4 sq,
                                           float4 mx, float4 mn, float* base) {
    float4 mean, var, sd;
    mean.x = su.x * inv; mean.y = su.y * inv; mean.z = su.z * inv; mean.w = su.w * inv;
    var.x = fmaxf(sq.x * inv - mean.x * mean.x, 0.f);
    var.y = fmaxf(sq.y * inv - mean.y * mean.y, 0.f);
    var.z = fmaxf(sq.z * inv - mean.z * mean.z, 0.f);
    var.w = fmaxf(sq.w * inv - mean.w * mean.w, 0.f);
    sd.x = sqrtf(var.x + 1e-5f); sd.y = sqrtf(var.y + 1e-5f);
    sd.z = sqrtf(var.z + 1e-5f); sd.w = sqrtf(var.w + 1e-5f);
    if (deg == 0) {
        mx = make_float4(0.f, 0.f, 0.f, 0.f);
        mn = make_float4(0.f, 0.f, 0.f, 0.f);
    }
    *(float4*)(base)       = mean;
    *(float4*)(base + 128) = mx;
    *(float4*)(base + 256) = mn;
    *(float4*)(base + 384) = sd;
}

__global__ __launch_bounds__(256) void k_agg(const int* __restrict__ cols,
                                             const float* __restrict__ vA,
                                             const float* __restrict__ vC, int N) {
    int warp = (blockIdx.x * blockDim.x + threadIdx.x) >> 5;
    int lane = threadIdx.x & 31;
    if (warp >= N) return;
    const int r0 = g_rowptr[warp], r1 = g_rowptr[warp + 1];

    const float NEG = -CUDART_INF_F, POS = CUDART_INF_F;
    float4 s1 = {0, 0, 0, 0}, q1 = {0, 0, 0, 0};
    float4 s2 = {0, 0, 0, 0}, q2 = {0, 0, 0, 0};
    float4 s3 = {0, 0, 0, 0}, q3 = {0, 0, 0, 0};
    float4 x1 = {NEG, NEG, NEG, NEG}, n1 = {POS, POS, POS, POS};
    float4 x2 = x1, n2 = n1, x3 = x1, n3 = n1;

    for (int e = r0; e < r1; e++) {
        int c = __ldg(cols + e);
        float a = __ldg(vA + e);
        float b = __ldg(vC + e);
        float h = a * b;
        const float* p = g_m + (size_t)c * 384 + lane * 4;
        float4 v1 = *(const float4*)(p);
        float4 v2 = *(const float4*)(p + 128);
        float4 v3 = *(const float4*)(p + 256);
        agg_upd(v1, a, s1, q1, x1, n1);
        agg_upd(v2, b, s2, q2, x2, n2);
        agg_upd(v3, h, s3, q3, x3, n3);
    }
    const int deg = r1 - r0;
    const float inv = 1.f / fmaxf((float)deg, 1.f);
    float* fb = g_feats + (size_t)warp * 1536 + lane * 4;
    agg_finish(deg, inv, s1, q1, x1, n1, fb);
    agg_finish(deg, inv, s2, q2, x2, n2, fb + 512);
    agg_finish(deg, inv, s3, q3, x3, n3, fb + 1024);
}

// ---------------- output GEMM (tf32 tensor cores) ----------------
// out = feats[N,1536] @ pw[1536,128] + sum(pna_b).  128x128 block tile, 8 warps
// in 2x4 grid, 64x32 warp tiles of m16n8k8 tf32 MMAs, cp.async double buffer.
#define APAD 20
#define BPAD 132
__global__ __launch_bounds__(256, 2) void k_out(const float* __restrict__ pw,
                                                const float* __restrict__ pb,
                                                float* __restrict__ out, int N) {
    __shared__ __align__(16) float As[2][128][APAD];
    __shared__ __align__(16) float Bs[2][16][BPAD];
    const int bm = blockIdx.x * 128;
    const int tid = threadIdx.x;
    const int lane = tid & 31;
    const int wid = tid >> 5;
    const int wm = wid >> 2;          // 0..1 : 64 rows
    const int wn = wid & 3;           // 0..3 : 32 cols
    const int tq = lane >> 2;         // 0..7
    const int tr = lane & 3;          // 0..3

    // staging mapping (same as SIMT version)
    const int ar0  = tid >> 2;        // 0..63
    const int akq  = (tid & 3) << 2;  // 0,4,8,12
    const int bkk0 = tid >> 5;        // 0..7
    const int bjq  = (tid & 31) << 2; // 0..124

    int gr0 = bm + ar0;      if (gr0 >= N) gr0 = N - 1;
    int gr1 = bm + ar0 + 64; if (gr1 >= N) gr1 = N - 1;
    const float* sA0 = g_feats + (size_t)gr0 * 1536 + akq;
    const float* sA1 = g_feats + (size_t)gr1 * 1536 + akq;
    const float* sB0 = pw + (size_t)bkk0 * 128 + bjq;
    const float* sB1 = pw + (size_t)(bkk0 + 8) * 128 + bjq;

    const unsigned ABUF = 128 * APAD * 4;  // bytes per As buffer
    const unsigned BBUF = 16 * BPAD * 4;   // bytes per Bs buffer
    const unsigned dA0 = (unsigned)__cvta_generic_to_shared(&As[0][ar0][akq]);
    const unsigned dA1 = (unsigned)__cvta_generic_to_shared(&As[0][ar0 + 64][akq]);
    const unsigned dB0 = (unsigned)__cvta_generic_to_shared(&Bs[0][bkk0][bjq]);
    const unsigned dB1 = (unsigned)__cvta_generic_to_shared(&Bs[0][bkk0 + 8][bjq]);

    const int NK = 96;  // chunks of k16
#pragma unroll
    for (int p = 0; p < 2; p++) {
        cpasync16(dA0 + p * ABUF, sA0 + p * 16);
        cpasync16(dA1 + p * ABUF, sA1 + p * 16);
        cpasync16(dB0 + p * BBUF, sB0 + (size_t)p * 2048);
        cpasync16(dB1 + p * BBUF, sB1 + (size_t)p * 2048);
        cp_commit();
    }

    float acc[4][4][4] = {};  // [mt][nt][reg]

    for (int i = 0; i < NK; i++) {
        cp_wait1();
        __syncthreads();
        const int buf = i & 1;
#pragma unroll
        for (int s = 0; s < 2; s++) {  // two k8 steps per chunk
            unsigned afr[4][4], bfr[4][2];
#pragma unroll
            for (int mt = 0; mt < 4; mt++) {
                const int r = wm * 64 + mt * 16 + tq;
                const int c = s * 8 + tr;
                afr[mt][0] = __float_as_uint(As[buf][r][c]);
                afr[mt][1] = __float_as_uint(As[buf][r + 8][c]);
                afr[mt][2] = __float_as_uint(As[buf][r][c + 4]);
                afr[mt][3] = __float_as_uint(As[buf][r + 8][c + 4]);
            }
#pragma unroll
            for (int nt = 0; nt < 4; nt++) {
                const int c = wn * 32 + nt * 8 + tq;
                bfr[nt][0] = __float_as_uint(Bs[buf][s * 8 + tr][c]);
                bfr[nt][1] = __float_as_uint(Bs[buf][s * 8 + tr + 4][c]);
            }
#pragma unroll
            for (int mt = 0; mt < 4; mt++)
#pragma unroll
                for (int nt = 0; nt < 4; nt++)
                    mma_tf32(acc[mt][nt], afr[mt], bfr[nt]);
        }
        __syncthreads();
        const int nc = i + 2;
        if (nc < NK) {
            cpasync16(dA0 + buf * ABUF, sA0 + nc * 16);
            cpasync16(dA1 + buf * ABUF, sA1 + nc * 16);
            cpasync16(dB0 + buf * BBUF, sB0 + (size_t)nc * 2048);
            cpasync16(dB1 + buf * BBUF, sB1 + (size_t)nc * 2048);
        }
        cp_commit();
    }

    // epilogue: bias = sum of 3 bias rows; each thread owns 2x2 per (mt,nt) tile
#pragma unroll
    for (int nt = 0; nt < 4; nt++) {
        const int c0 = wn * 32 + nt * 8 + 2 * tr;
        const float b0 = __ldg(pb + c0) + __ldg(pb + 128 + c0) + __ldg(pb + 256 + c0);
        const float b1 = __ldg(pb + c0 + 1) + __ldg(pb + 128 + c0 + 1) + __ldg(pb + 256 + c0 + 1);
#pragma unroll
        for (int mt = 0; mt < 4; mt++) {
            const int r0 = bm + wm * 64 + mt * 16 + tq;
            if (r0 < N) {
                float2 v = make_float2(acc[mt][nt][0] + b0, acc[mt][nt][1] + b1);
                *(float2*)&out[(size_t)r0 * 128 + c0] = v;
            }
            const int r1 = r0 + 8;
            if (r1 < N) {
                float2 v = make_float2(acc[mt][nt][2] + b0, acc[mt][nt][3] + b1);
                *(float2*)&out[(size_t)r1 * 128 + c0] = v;
            }
        }
    }
}

// ---------------- launch ----------------
extern "C" void kernel_launch(void* const* d_in, const int* in_sizes, int n_in,
                              void* d_out, int out_size) {
    const float* x    = (const float*)d_in[0];
    const int*   rows = (const int*)d_in[1];
    const int*   cols = (const int*)d_in[2];
    const float* vA   = (const float*)d_in[3];
    const float* vC   = (const float*)d_in[4];
    const float* W    = (const float*)d_in[5];
    const float* W2   = (const float*)d_in[6];
    const float* W3   = (const float*)d_in[7];
    const float* pw   = (const float*)d_in[8];  // [3,512,128] == flat [1536,128]
    const float* pb   = (const float*)d_in[9];  // [3,128]
    float* out = (float*)d_out;

    const int N = in_sizes[0] / 128;
    const int E = in_sizes[1];

    k_rowptr<<<(N + 1 + 255) / 256, 256>>>(rows, E, N);
    dim3 gproj((N + 127) / 128, 3);
    k_proj<<<gproj, 256>>>(x, W, W2, W3, N);
    k_agg<<<(N + 7) / 8, 256>>>(cols, vA, vC, N);
    k_out<<<(N + 127) / 128, 256>>>(pw, pb, out, N);
}